// round 12
// baseline (speedup 1.0000x reference)
#include <cuda_runtime.h>
#include <cuda_fp16.h>
#include <cstdint>

// ============================================================================
// Problem constants (fixed shapes for SVMModel_19267223290147)
// ============================================================================
#define BB 2048      // batch rows
#define NN 32768     // train rows
#define DD 128       // feature dim
#define BT 128       // CTA B-tile (M)
#define NT 128       // CTA N-tile
#define NSPLITS 8    // N chunks across grid.x
#define BTILES  16   // B tiles across grid.y
#define NCHUNK (NN / NSPLITS)     // 4096
#define TILES  (NCHUNK / NT)      // 32
#define THREADS 512  // 16 warps = 4/SMSP (latency hiding), 4m x 4n grid

// SMEM layout: A tile + double-buffered B tiles + double-buffered c1 slices.
#define SMEM_A   0
#define SMEM_B0  32768
#define SMEM_B1  65536
#define SMEM_C10 98304
#define SMEM_C11 98816
#define SMEM_TOTAL 99328

#define SWZ(o) ((o) ^ (((o) >> 3) & 0x70))

// ============================================================================
// Device globals (static allocation: allowed)
// ============================================================================
__device__ __half g_xbf[BB * DD];              // x * (2*gamma*log2e) fp16
__device__ __half g_tbf[NN * DD];              // train_data fp16
__device__ float  g_c1[NN];                    // W[n] * exp(-g*t2[n])
__device__ float  g_ex[BB];                    // exp(-g*x2[b])
__device__ float  g_partial[NSPLITS * BB * 4]; // (ns, b, warp_n quarter)

// ============================================================================
// PTX helpers (sm_100 base-target safe)
// ============================================================================
__device__ __forceinline__ uint32_t smem_u32(const void* p) {
    uint32_t a;
    asm("{ .reg .u64 t; cvta.to.shared.u64 t, %1; cvt.u32.u64 %0, t; }" : "=r"(a) : "l"(p));
    return a;
}
__device__ __forceinline__ float ex2f(float x) {
    float y; asm("ex2.approx.f32 %0, %1;" : "=f"(y) : "f"(x)); return y;
}
__device__ __forceinline__ float2 lds64f(uint32_t addr) {
    float2 v;
    asm volatile("ld.shared.v2.f32 {%0, %1}, [%2];" : "=f"(v.x), "=f"(v.y) : "r"(addr));
    return v;
}
__device__ __forceinline__ void cp_async16(uint32_t dst, const void* src) {
    asm volatile("cp.async.cg.shared.global [%0], [%1], 16;" :: "r"(dst), "l"(src));
}
#define CP_COMMIT() asm volatile("cp.async.commit_group;" ::: "memory")

__device__ __forceinline__ void ldsm4(uint32_t* r, uint32_t addr) {
    asm volatile("ldmatrix.sync.aligned.m8n8.x4.shared.b16 {%0,%1,%2,%3}, [%4];"
                 : "=r"(r[0]), "=r"(r[1]), "=r"(r[2]), "=r"(r[3]) : "r"(addr));
}
__device__ __forceinline__ void mma16816(float* c, const uint32_t* a, const uint32_t* b) {
    asm volatile(
        "mma.sync.aligned.m16n8k16.row.col.f32.f16.f16.f32 "
        "{%0,%1,%2,%3}, {%4,%5,%6,%7}, {%8,%9}, {%0,%1,%2,%3};"
        : "+f"(c[0]), "+f"(c[1]), "+f"(c[2]), "+f"(c[3])
        : "r"(a[0]), "r"(a[1]), "r"(a[2]), "r"(a[3]), "r"(b[0]), "r"(b[1]));
}

// cp.async one [128 x 128 fp16] tile into SMEM (chunked SW128 layout).
// 2048 16-byte pieces, 4 per thread (512 threads), coalesced in GMEM.
__device__ __forceinline__ void issue_tile(uint32_t sm_base, const __half* src) {
    int tid = threadIdx.x;
    #pragma unroll
    for (int it = 0; it < 4; it++) {
        int k = tid + it * 512;
        int row = k >> 4;
        int rem = k & 15;
        int c = rem >> 3;
        int j = rem & 7;
        uint32_t dst = sm_base + c * 16384 + SWZ((uint32_t)(row * 128 + j * 16));
        cp_async16(dst, src + row * 128 + c * 64 + j * 8);
    }
}

// cp.async the 512B c1 slice for one tile (threads 0..31, 16B each).
__device__ __forceinline__ void issue_c1(uint32_t sm_c1, const float* src) {
    int tid = threadIdx.x;
    if (tid < 32) cp_async16(sm_c1 + tid * 16, src + tid * 4);
}

// ============================================================================
// Merged prep kernel (R8-proven): rows [0,BB) = x, rows [BB,BB+NN) = t.
// fp32 norms; x pre-scaled by 2*gamma*log2(e).
// ============================================================================
__global__ void prep_kernel(const float* __restrict__ x, const float* __restrict__ train,
                            const float* __restrict__ gamma, const float* __restrict__ W) {
    int w = (blockIdx.x * blockDim.x + threadIdx.x) >> 5;
    int lane = threadIdx.x & 31;
    float gm = gamma[0];
    if (w < BB) {
        float s = 2.0f * gm * 1.4426950408889634f;
        float4 v = reinterpret_cast<const float4*>(x + (size_t)w * DD)[lane];
        float ss = v.x * v.x + v.y * v.y + v.z * v.z + v.w * v.w;
        #pragma unroll
        for (int o = 16; o > 0; o >>= 1) ss += __shfl_xor_sync(0xFFFFFFFFu, ss, o);
        __half2* dst = reinterpret_cast<__half2*>(g_xbf + (size_t)w * DD + lane * 4);
        dst[0] = __floats2half2_rn(v.x * s, v.y * s);
        dst[1] = __floats2half2_rn(v.z * s, v.w * s);
        if (lane == 0) g_ex[w] = expf(-gm * ss);
    } else {
        int r = w - BB;
        if (r >= NN) return;
        float4 v = reinterpret_cast<const float4*>(train + (size_t)r * DD)[lane];
        float ss = v.x * v.x + v.y * v.y + v.z * v.z + v.w * v.w;
        #pragma unroll
        for (int o = 16; o > 0; o >>= 1) ss += __shfl_xor_sync(0xFFFFFFFFu, ss, o);
        __half2* dst = reinterpret_cast<__half2*>(g_tbf + (size_t)r * DD + lane * 4);
        dst[0] = __floats2half2_rn(v.x, v.y);
        dst[1] = __floats2half2_rn(v.z, v.w);
        if (lane == 0) g_c1[r] = W[r] * expf(-gm * ss);
    }
}

// ============================================================================
// Main kernel: 512 threads, 4m x 4n warps (each 32x32 out), NO A-hoist.
// Per tile: loop kq { ldsm A+B frags, 16 MMAs (8 indep chains) }, then epilogue.
// ~90 live regs -> no spills at the 128-reg/thread cap.
// ============================================================================
__global__ void __launch_bounds__(THREADS, 1)
rbf_main_kernel() {
    extern __shared__ char smem[];
    uint32_t sb = smem_u32(smem);
    int tid = threadIdx.x;
    int lane = tid & 31;
    int wid = tid >> 5;
    int warp_m = wid & 3;     // 4 warps along M (32 rows each); = SMSP id
    int warp_n = wid >> 2;    // 4 warps along N (32 cols each)
    int g  = lane >> 2;
    int tg = lane & 3;

    int m0 = blockIdx.y * BT;
    int ns = blockIdx.x;
    int n_base = ns * NCHUNK;

    // Prologue: A tile + (B0,c1_0) group 0, (B1,c1_1) group 1
    issue_tile(sb + SMEM_A, g_xbf + (size_t)m0 * DD);
    issue_tile(sb + SMEM_B0, g_tbf + (size_t)n_base * DD);
    issue_c1(sb + SMEM_C10, g_c1 + n_base);
    CP_COMMIT();
    issue_tile(sb + SMEM_B1, g_tbf + (size_t)(n_base + NT) * DD);
    issue_c1(sb + SMEM_C11, g_c1 + n_base + NT);
    CP_COMMIT();

    int a_row_in_warp = ((lane >> 3) & 1) * 8 + (lane & 7);
    int a_kb16 = ((lane >> 4) & 1) * 16;
    int b_row_in_nb = lane & 7;
    int b_kb16 = (lane >> 3) * 16;

    // Precompute per-kq ldsm addresses' row components
    int a_row0 = warp_m * 32 + a_row_in_warp;          // ms=0 row
    int b_row0 = warp_n * 32 + b_row_in_nb;            // nb=0 row

    asm volatile("cp.async.wait_group 1;" ::: "memory");  // A + B0 + c1_0 resident
    __syncthreads();

    float racc[2][2] = {{0.f, 0.f}, {0.f, 0.f}};

    for (int i = 0; i < TILES; i++) {
        if (i + 1 < TILES) { asm volatile("cp.async.wait_group 1;" ::: "memory"); }
        else               { asm volatile("cp.async.wait_group 0;" ::: "memory"); }
        __syncthreads();

        uint32_t Bb  = sb + ((i & 1) ? SMEM_B1  : SMEM_B0);
        uint32_t c1s = sb + ((i & 1) ? SMEM_C11 : SMEM_C10) + (warp_n * 32 + 2 * tg) * 4;

        float acc[4][2][4];     // [nb][ms][4] = 32 regs, whole-tile accumulators
        #pragma unroll
        for (int nb = 0; nb < 4; nb++)
            #pragma unroll
            for (int ms = 0; ms < 2; ms++)
                #pragma unroll
                for (int c = 0; c < 4; c++) acc[nb][ms][c] = 0.f;

        // K loop: transient A/B fragments per kq (16+16 regs), 16 MMAs each.
        #pragma unroll
        for (int kq = 0; kq < 4; kq++) {
            int chunk = kq >> 1;
            int kbyte0 = (kq & 1) * 64;
            uint32_t a_base = sb + SMEM_A + chunk * 16384;
            uint32_t b_base = Bb + chunk * 16384;

            uint32_t af[2][2][4];   // [ms][kk][4]
            #pragma unroll
            for (int ms = 0; ms < 2; ms++) {
                int row = a_row0 + ms * 16;
                ldsm4(af[ms][0], a_base + SWZ((uint32_t)(row * 128 + kbyte0 + a_kb16)));
                ldsm4(af[ms][1], a_base + SWZ((uint32_t)(row * 128 + kbyte0 + 32 + a_kb16)));
            }
            uint32_t bf[4][4];      // [nb][k-sub]
            #pragma unroll
            for (int nb = 0; nb < 4; nb++) {
                int row = b_row0 + nb * 8;
                ldsm4(bf[nb], b_base + SWZ((uint32_t)(row * 128 + kbyte0 + b_kb16)));
            }
            // kk -> nb -> ms: 8 independent chains within this kq.
            #pragma unroll
            for (int kk = 0; kk < 2; kk++)
                #pragma unroll
                for (int nb = 0; nb < 4; nb++)
                    #pragma unroll
                    for (int ms = 0; ms < 2; ms++)
                        mma16816(acc[nb][ms], af[ms][kk], &bf[nb][kk * 2]);
        }

        // Epilogue: ex2 + fma; other warps' MMA phases overlap this (4/SMSP).
        #pragma unroll
        for (int nb = 0; nb < 4; nb++) {
            float2 w = lds64f(c1s + nb * 32);
            #pragma unroll
            for (int ms = 0; ms < 2; ms++) {
                racc[ms][0] = fmaf(ex2f(acc[nb][ms][0]), w.x, racc[ms][0]);
                racc[ms][0] = fmaf(ex2f(acc[nb][ms][1]), w.y, racc[ms][0]);
                racc[ms][1] = fmaf(ex2f(acc[nb][ms][2]), w.x, racc[ms][1]);
                racc[ms][1] = fmaf(ex2f(acc[nb][ms][3]), w.y, racc[ms][1]);
            }
        }

        __syncthreads();   // all warps done reading Bb + c1s
        if (i + 2 < TILES) {
            issue_tile(Bb, g_tbf + (size_t)(n_base + (i + 2) * NT) * DD);
            issue_c1(sb + ((i & 1) ? SMEM_C11 : SMEM_C10), g_c1 + n_base + (i + 2) * NT);
        }
        CP_COMMIT();
    }

    // Reduce over the 4 lanes sharing each row, write deterministic partials.
    #pragma unroll
    for (int ms = 0; ms < 2; ms++)
        #pragma unroll
        for (int h = 0; h < 2; h++) {
            float v = racc[ms][h];
            v += __shfl_xor_sync(0xFFFFFFFFu, v, 1);
            v += __shfl_xor_sync(0xFFFFFFFFu, v, 2);
            if (tg == 0) {
                int b = m0 + warp_m * 32 + ms * 16 + h * 8 + g;
                g_partial[(ns * BB + b) * 4 + warp_n] = v;
            }
        }
}

// ============================================================================
// Final reduction: out[b] = e_x[b] * sum(partials) + bias
// ============================================================================
__global__ void reduce_kernel(const float* __restrict__ bias, float* __restrict__ out) {
    int b = blockIdx.x * blockDim.x + threadIdx.x;
    if (b >= BB) return;
    float s = 0.0f;
    #pragma unroll
    for (int ns = 0; ns < NSPLITS; ns++)
        #pragma unroll
        for (int q = 0; q < 4; q++)
            s += g_partial[(ns * BB + b) * 4 + q];
    out[b] = fmaf(g_ex[b], s, __ldg(bias));
}

// ============================================================================
// Entry — 3 launches (merged prep, main, reduce)
// ============================================================================
extern "C" void kernel_launch(void* const* d_in, const int* in_sizes, int n_in,
                              void* d_out, int out_size) {
    const float* x     = (const float*)d_in[0];   // [2048, 128]
    const float* train = (const float*)d_in[1];   // [32768, 128]
    const float* gamma = (const float*)d_in[2];   // [1]
    const float* W     = (const float*)d_in[3];   // [1, 32768]
    const float* bias  = (const float*)d_in[4];   // [1]
    float* out = (float*)d_out;                   // [2048, 1]

    cudaFuncSetAttribute(rbf_main_kernel,
                         cudaFuncAttributeMaxDynamicSharedMemorySize, SMEM_TOTAL);

    prep_kernel<<<((BB + NN) * 32) / 256, 256>>>(x, train, gamma, W);
    rbf_main_kernel<<<dim3(NSPLITS, BTILES), THREADS, SMEM_TOTAL>>>();
    reduce_kernel<<<BB / 256, 256>>>(bias, out);
}

// round 13
// speedup vs baseline: 1.0882x; 1.0882x over previous
#include <cuda_runtime.h>
#include <cuda_fp16.h>
#include <cstdint>

// ============================================================================
// Problem constants (fixed shapes for SVMModel_19267223290147)
// ============================================================================
#define BB 2048      // batch rows
#define NN 32768     // train rows
#define DD 128       // feature dim
#define BT 128       // CTA B-tile (M)
#define NT 128       // CTA N-tile
#define NSPLITS 8    // N chunks across grid.x
#define BTILES  16   // B tiles across grid.y
#define NCHUNK (NN / NSPLITS)     // 4096
#define TILES  (NCHUNK / NT)      // 32
#define THREADS 256

// SMEM layout: A tile + double-buffered B tiles + double-buffered c1 slices.
#define SMEM_A   0
#define SMEM_B0  32768
#define SMEM_B1  65536
#define SMEM_C10 98304
#define SMEM_C11 98816
#define SMEM_TOTAL 99328

#define SWZ(o) ((o) ^ (((o) >> 3) & 0x70))

// ============================================================================
// Device globals (static allocation: allowed)
// ============================================================================
__device__ __half g_xbf[BB * DD];              // x * (2*gamma*log2e) fp16
__device__ __half g_tbf[NN * DD];              // train_data fp16
__device__ float  g_c1[NN];                    // W[n] * exp(-g*t2[n])
__device__ float  g_ex[BB];                    // exp(-g*x2[b])
__device__ float  g_partial[NSPLITS * BB * 2];

// ============================================================================
// PTX helpers (sm_100 base-target safe)
// ============================================================================
__device__ __forceinline__ uint32_t smem_u32(const void* p) {
    uint32_t a;
    asm("{ .reg .u64 t; cvta.to.shared.u64 t, %1; cvt.u32.u64 %0, t; }" : "=r"(a) : "l"(p));
    return a;
}
__device__ __forceinline__ float ex2f(float x) {
    float y; asm("ex2.approx.f32 %0, %1;" : "=f"(y) : "f"(x)); return y;
}
__device__ __forceinline__ float2 lds64f(uint32_t addr) {
    float2 v;
    asm volatile("ld.shared.v2.f32 {%0, %1}, [%2];" : "=f"(v.x), "=f"(v.y) : "r"(addr));
    return v;
}
__device__ __forceinline__ void cp_async16(uint32_t dst, const void* src) {
    asm volatile("cp.async.cg.shared.global [%0], [%1], 16;" :: "r"(dst), "l"(src));
}
#define CP_COMMIT() asm volatile("cp.async.commit_group;" ::: "memory")

__device__ __forceinline__ void ldsm4(uint32_t* r, uint32_t addr) {
    asm volatile("ldmatrix.sync.aligned.m8n8.x4.shared.b16 {%0,%1,%2,%3}, [%4];"
                 : "=r"(r[0]), "=r"(r[1]), "=r"(r[2]), "=r"(r[3]) : "r"(addr));
}
__device__ __forceinline__ void mma16816(float* c, const uint32_t* a, const uint32_t* b) {
    asm volatile(
        "mma.sync.aligned.m16n8k16.row.col.f32.f16.f16.f32 "
        "{%0,%1,%2,%3}, {%4,%5,%6,%7}, {%8,%9}, {%0,%1,%2,%3};"
        : "+f"(c[0]), "+f"(c[1]), "+f"(c[2]), "+f"(c[3])
        : "r"(a[0]), "r"(a[1]), "r"(a[2]), "r"(a[3]), "r"(b[0]), "r"(b[1]));
}

// cp.async one [128 x 128 fp16] tile into SMEM (chunked SW128 layout).
__device__ __forceinline__ void issue_tile(uint32_t sm_base, const __half* src) {
    int tid = threadIdx.x;
    #pragma unroll
    for (int it = 0; it < 8; it++) {
        int k = tid + it * 256;
        int row = k >> 4;
        int rem = k & 15;
        int c = rem >> 3;
        int j = rem & 7;
        uint32_t dst = sm_base + c * 16384 + SWZ((uint32_t)(row * 128 + j * 16));
        cp_async16(dst, src + row * 128 + c * 64 + j * 8);
    }
}

// cp.async the 512B c1 slice for one tile (threads 0..31, 16B each).
__device__ __forceinline__ void issue_c1(uint32_t sm_c1, const float* src) {
    int tid = threadIdx.x;
    if (tid < 32) cp_async16(sm_c1 + tid * 16, src + tid * 4);
}

// ============================================================================
// Prep kernels (fp32 norms; x pre-scaled by 2*gamma*log2e)
// ============================================================================
__global__ void prep_x_kernel(const float* __restrict__ x, const float* __restrict__ gamma) {
    int w = (blockIdx.x * blockDim.x + threadIdx.x) >> 5;
    int lane = threadIdx.x & 31;
    if (w >= BB) return;
    float gm = gamma[0];
    float s = 2.0f * gm * 1.4426950408889634f;
    float4 v = reinterpret_cast<const float4*>(x + w * DD)[lane];
    float ss = v.x * v.x + v.y * v.y + v.z * v.z + v.w * v.w;
    #pragma unroll
    for (int o = 16; o > 0; o >>= 1) ss += __shfl_xor_sync(0xFFFFFFFFu, ss, o);
    __half2* dst = reinterpret_cast<__half2*>(g_xbf + w * DD + lane * 4);
    dst[0] = __floats2half2_rn(v.x * s, v.y * s);
    dst[1] = __floats2half2_rn(v.z * s, v.w * s);
    if (lane == 0) g_ex[w] = expf(-gm * ss);
}

__global__ void prep_t_kernel(const float* __restrict__ t, const float* __restrict__ gamma,
                              const float* __restrict__ W) {
    int w = (blockIdx.x * blockDim.x + threadIdx.x) >> 5;
    int lane = threadIdx.x & 31;
    if (w >= NN) return;
    float4 v = reinterpret_cast<const float4*>(t + w * DD)[lane];
    float ss = v.x * v.x + v.y * v.y + v.z * v.z + v.w * v.w;
    #pragma unroll
    for (int o = 16; o > 0; o >>= 1) ss += __shfl_xor_sync(0xFFFFFFFFu, ss, o);
    __half2* dst = reinterpret_cast<__half2*>(g_tbf + w * DD + lane * 4);
    dst[0] = __floats2half2_rn(v.x, v.y);
    dst[1] = __floats2half2_rn(v.z, v.w);
    if (lane == 0) g_c1[w] = W[w] * expf(-gamma[0] * ss);
}

// ============================================================================
// Main kernel: R11 structure; ONLY change = epilogue software-pipelined one
// pair behind the MMAs (acc double-buffered by pair parity), so the MUFU
// throttle of pair p drains under the tensor work of pair p+1.
// ============================================================================
__global__ void __launch_bounds__(THREADS, 1)
rbf_main_kernel() {
    extern __shared__ char smem[];
    uint32_t sb = smem_u32(smem);
    int tid = threadIdx.x;
    int lane = tid & 31;
    int wid = tid >> 5;
    int warp_m = wid & 3;     // 4 warps along M (32 rows each)
    int warp_n = wid >> 2;    // 2 warps along N (64 cols each)
    int g  = lane >> 2;
    int tg = lane & 3;

    int m0 = blockIdx.y * BT;
    int ns = blockIdx.x;
    int n_base = ns * NCHUNK;

    // Prologue: A tile + (B0,c1_0) group 0, (B1,c1_1) group 1
    issue_tile(sb + SMEM_A, g_xbf + (size_t)m0 * DD);
    issue_tile(sb + SMEM_B0, g_tbf + (size_t)n_base * DD);
    issue_c1(sb + SMEM_C10, g_c1 + n_base);
    CP_COMMIT();
    issue_tile(sb + SMEM_B1, g_tbf + (size_t)(n_base + NT) * DD);
    issue_c1(sb + SMEM_C11, g_c1 + n_base + NT);
    CP_COMMIT();

    int a_row_in_warp = ((lane >> 3) & 1) * 8 + (lane & 7);
    int a_kb16 = ((lane >> 4) & 1) * 16;
    int b_row_in_nb = lane & 7;
    int b_kb16 = (lane >> 3) * 16;

    asm volatile("cp.async.wait_group 1;" ::: "memory");  // A + B0 + c1_0 resident
    __syncthreads();

    // Hoist A fragments (constant across the whole tile loop)
    uint32_t af[4][2][2][4];   // [kq][ms][kk][4]
    #pragma unroll
    for (int kq = 0; kq < 4; kq++) {
        int chunk = kq >> 1;
        int kbyte0 = (kq & 1) * 64;
        uint32_t base = sb + SMEM_A + chunk * 16384;
        #pragma unroll
        for (int ms = 0; ms < 2; ms++) {
            int row = warp_m * 32 + ms * 16 + a_row_in_warp;
            ldsm4(af[kq][ms][0], base + SWZ((uint32_t)(row * 128 + kbyte0 + a_kb16)));
            ldsm4(af[kq][ms][1], base + SWZ((uint32_t)(row * 128 + kbyte0 + 32 + a_kb16)));
        }
    }

    float racc[2][2] = {{0.f, 0.f}, {0.f, 0.f}};

    for (int i = 0; i < TILES; i++) {
        if (i + 1 < TILES) { asm volatile("cp.async.wait_group 1;" ::: "memory"); }
        else               { asm volatile("cp.async.wait_group 0;" ::: "memory"); }
        __syncthreads();

        uint32_t Bb  = sb + ((i & 1) ? SMEM_B1  : SMEM_B0);
        uint32_t c1s = sb + ((i & 1) ? SMEM_C11 : SMEM_C10) + (warp_n * 64 + 2 * tg) * 4;

        // Pair-pipelined: MMA(p) issued, epilogue(p-1) follows — its MUFU
        // work drains while pair p's HMMAs occupy the tensor pipe.
        float acc[2][2][2][4];   // [parity][nb2][ms][4]
        float2 wv[2][2];         // [parity][nb2]

        #pragma unroll
        for (int np = 0; np < 4; np++) {
            int p = np & 1;
            uint32_t bf[2][4][4];   // [nb2][kq][k-sub]
            #pragma unroll
            for (int nb2 = 0; nb2 < 2; nb2++) {
                int row = warp_n * 64 + (np * 2 + nb2) * 8 + b_row_in_nb;
                #pragma unroll
                for (int kq = 0; kq < 4; kq++) {
                    int chunk = kq >> 1;
                    int kbyte0 = (kq & 1) * 64;
                    ldsm4(bf[nb2][kq], Bb + chunk * 16384 +
                          SWZ((uint32_t)(row * 128 + kbyte0 + b_kb16)));
                }
            }
            #pragma unroll
            for (int nb2 = 0; nb2 < 2; nb2++) {
                wv[p][nb2] = lds64f(c1s + (np * 2 + nb2) * 32);
                #pragma unroll
                for (int ms = 0; ms < 2; ms++)
                    #pragma unroll
                    for (int c = 0; c < 4; c++) acc[p][nb2][ms][c] = 0.f;
            }
            // kq -> kk -> nb2 -> ms: same-chain MMAs are 4 issues apart.
            #pragma unroll
            for (int kq = 0; kq < 4; kq++)
                #pragma unroll
                for (int kk = 0; kk < 2; kk++)
                    #pragma unroll
                    for (int nb2 = 0; nb2 < 2; nb2++)
                        #pragma unroll
                        for (int ms = 0; ms < 2; ms++)
                            mma16816(acc[p][nb2][ms], af[kq][ms][kk], &bf[nb2][kq][kk * 2]);

            if (np > 0) {  // epilogue of the PREVIOUS pair (parity p^1)
                int q = p ^ 1;
                #pragma unroll
                for (int nb2 = 0; nb2 < 2; nb2++) {
                    #pragma unroll
                    for (int ms = 0; ms < 2; ms++) {
                        racc[ms][0] = fmaf(ex2f(acc[q][nb2][ms][0]), wv[q][nb2].x, racc[ms][0]);
                        racc[ms][0] = fmaf(ex2f(acc[q][nb2][ms][1]), wv[q][nb2].y, racc[ms][0]);
                        racc[ms][1] = fmaf(ex2f(acc[q][nb2][ms][2]), wv[q][nb2].x, racc[ms][1]);
                        racc[ms][1] = fmaf(ex2f(acc[q][nb2][ms][3]), wv[q][nb2].y, racc[ms][1]);
                    }
                }
            }
        }
        // Drain epilogue of the last pair (np=3, parity 1)
        #pragma unroll
        for (int nb2 = 0; nb2 < 2; nb2++) {
            #pragma unroll
            for (int ms = 0; ms < 2; ms++) {
                racc[ms][0] = fmaf(ex2f(acc[1][nb2][ms][0]), wv[1][nb2].x, racc[ms][0]);
                racc[ms][0] = fmaf(ex2f(acc[1][nb2][ms][1]), wv[1][nb2].y, racc[ms][0]);
                racc[ms][1] = fmaf(ex2f(acc[1][nb2][ms][2]), wv[1][nb2].x, racc[ms][1]);
                racc[ms][1] = fmaf(ex2f(acc[1][nb2][ms][3]), wv[1][nb2].y, racc[ms][1]);
            }
        }

        __syncthreads();   // all warps done reading Bb + c1s
        if (i + 2 < TILES) {
            issue_tile(Bb, g_tbf + (size_t)(n_base + (i + 2) * NT) * DD);
            issue_c1(sb + ((i & 1) ? SMEM_C11 : SMEM_C10), g_c1 + n_base + (i + 2) * NT);
        }
        CP_COMMIT();
    }

    // Reduce over the 4 lanes sharing each row, write deterministic partials.
    #pragma unroll
    for (int ms = 0; ms < 2; ms++)
        #pragma unroll
        for (int h = 0; h < 2; h++) {
            float v = racc[ms][h];
            v += __shfl_xor_sync(0xFFFFFFFFu, v, 1);
            v += __shfl_xor_sync(0xFFFFFFFFu, v, 2);
            if (tg == 0) {
                int b = m0 + warp_m * 32 + ms * 16 + h * 8 + g;
                g_partial[(ns * BB + b) * 2 + warp_n] = v;
            }
        }
}

// ============================================================================
// Final reduction: out[b] = e_x[b] * sum(partials) + bias
// ============================================================================
__global__ void reduce_kernel(const float* __restrict__ bias, float* __restrict__ out) {
    int b = blockIdx.x * blockDim.x + threadIdx.x;
    if (b >= BB) return;
    float s = 0.0f;
    #pragma unroll
    for (int ns = 0; ns < NSPLITS; ns++) {
        s += g_partial[(ns * BB + b) * 2 + 0];
        s += g_partial[(ns * BB + b) * 2 + 1];
    }
    out[b] = fmaf(g_ex[b], s, __ldg(bias));
}

// ============================================================================
// Entry — 4-launch structure (R11-proven)
// ============================================================================
extern "C" void kernel_launch(void* const* d_in, const int* in_sizes, int n_in,
                              void* d_out, int out_size) {
    const float* x     = (const float*)d_in[0];   // [2048, 128]
    const float* train = (const float*)d_in[1];   // [32768, 128]
    const float* gamma = (const float*)d_in[2];   // [1]
    const float* W     = (const float*)d_in[3];   // [1, 32768]
    const float* bias  = (const float*)d_in[4];   // [1]
    float* out = (float*)d_out;                   // [2048, 1]

    cudaFuncSetAttribute(rbf_main_kernel,
                         cudaFuncAttributeMaxDynamicSharedMemorySize, SMEM_TOTAL);

    prep_x_kernel<<<(BB * 32) / THREADS, THREADS>>>(x, gamma);
    prep_t_kernel<<<(NN * 32) / THREADS, THREADS>>>(train, gamma, W);
    rbf_main_kernel<<<dim3(NSPLITS, BTILES), THREADS, SMEM_TOTAL>>>();
    reduce_kernel<<<BB / THREADS, THREADS>>>(bias, out);
}

// round 14
// speedup vs baseline: 1.2199x; 1.1210x over previous
#include <cuda_runtime.h>
#include <cuda_fp16.h>
#include <cstdint>

// ============================================================================
// Problem constants (fixed shapes for SVMModel_19267223290147)
// ============================================================================
#define BB 2048      // batch rows
#define NN 32768     // train rows
#define DD 128       // feature dim
#define BT 128       // CTA B-tile (M)
#define NT 128       // CTA N-tile
#define NSPLITS 9    // ragged N chunks across grid.x (29,29,29,29,28,28,28,28,28)
#define BTILES  16   // B tiles across grid.y
#define NTILES_TOTAL (NN / NT)    // 256
#define THREADS 256
#define PSLOTS (NSPLITS * 2)      // 18 partial slots per b row

// SMEM layout: A tile + double-buffered B tiles + double-buffered c1 slices.
#define SMEM_A   0
#define SMEM_B0  32768
#define SMEM_B1  65536
#define SMEM_C10 98304
#define SMEM_C11 98816
#define SMEM_TOTAL 99328

#define SWZ(o) ((o) ^ (((o) >> 3) & 0x70))

// ============================================================================
// Device globals (static allocation: allowed)
// ============================================================================
__device__ __half g_xbf[BB * DD];              // x * (2*gamma*log2e) fp16
__device__ __half g_tbf[NN * DD];              // train_data fp16
__device__ float  g_c1[NN];                    // W[n] * exp(-g*t2[n])
__device__ float  g_ex[BB];                    // exp(-g*x2[b])
__device__ float  g_partial[BB * PSLOTS];      // [b][ns*2+warp_n], contiguous per b

// ============================================================================
// PTX helpers (sm_100 base-target safe)
// ============================================================================
__device__ __forceinline__ uint32_t smem_u32(const void* p) {
    uint32_t a;
    asm("{ .reg .u64 t; cvta.to.shared.u64 t, %1; cvt.u32.u64 %0, t; }" : "=r"(a) : "l"(p));
    return a;
}
__device__ __forceinline__ float ex2f(float x) {
    float y; asm("ex2.approx.f32 %0, %1;" : "=f"(y) : "f"(x)); return y;
}
__device__ __forceinline__ float2 lds64f(uint32_t addr) {
    float2 v;
    asm volatile("ld.shared.v2.f32 {%0, %1}, [%2];" : "=f"(v.x), "=f"(v.y) : "r"(addr));
    return v;
}
__device__ __forceinline__ void cp_async16(uint32_t dst, const void* src) {
    asm volatile("cp.async.cg.shared.global [%0], [%1], 16;" :: "r"(dst), "l"(src));
}
#define CP_COMMIT() asm volatile("cp.async.commit_group;" ::: "memory")

__device__ __forceinline__ void ldsm4(uint32_t* r, uint32_t addr) {
    asm volatile("ldmatrix.sync.aligned.m8n8.x4.shared.b16 {%0,%1,%2,%3}, [%4];"
                 : "=r"(r[0]), "=r"(r[1]), "=r"(r[2]), "=r"(r[3]) : "r"(addr));
}
__device__ __forceinline__ void mma16816(float* c, const uint32_t* a, const uint32_t* b) {
    asm volatile(
        "mma.sync.aligned.m16n8k16.row.col.f32.f16.f16.f32 "
        "{%0,%1,%2,%3}, {%4,%5,%6,%7}, {%8,%9}, {%0,%1,%2,%3};"
        : "+f"(c[0]), "+f"(c[1]), "+f"(c[2]), "+f"(c[3])
        : "r"(a[0]), "r"(a[1]), "r"(a[2]), "r"(a[3]), "r"(b[0]), "r"(b[1]));
}

// cp.async one [128 x 128 fp16] tile into SMEM (chunked SW128 layout).
__device__ __forceinline__ void issue_tile(uint32_t sm_base, const __half* src) {
    int tid = threadIdx.x;
    #pragma unroll
    for (int it = 0; it < 8; it++) {
        int k = tid + it * 256;
        int row = k >> 4;
        int rem = k & 15;
        int c = rem >> 3;
        int j = rem & 7;
        uint32_t dst = sm_base + c * 16384 + SWZ((uint32_t)(row * 128 + j * 16));
        cp_async16(dst, src + row * 128 + c * 64 + j * 8);
    }
}

// cp.async the 512B c1 slice for one tile (threads 0..31, 16B each).
__device__ __forceinline__ void issue_c1(uint32_t sm_c1, const float* src) {
    int tid = threadIdx.x;
    if (tid < 32) cp_async16(sm_c1 + tid * 16, src + tid * 4);
}

// ============================================================================
// Prep kernels (fp32 norms; x pre-scaled by 2*gamma*log2e)
// ============================================================================
__global__ void prep_x_kernel(const float* __restrict__ x, const float* __restrict__ gamma) {
    int w = (blockIdx.x * blockDim.x + threadIdx.x) >> 5;
    int lane = threadIdx.x & 31;
    if (w >= BB) return;
    float gm = gamma[0];
    float s = 2.0f * gm * 1.4426950408889634f;
    float4 v = reinterpret_cast<const float4*>(x + w * DD)[lane];
    float ss = v.x * v.x + v.y * v.y + v.z * v.z + v.w * v.w;
    #pragma unroll
    for (int o = 16; o > 0; o >>= 1) ss += __shfl_xor_sync(0xFFFFFFFFu, ss, o);
    __half2* dst = reinterpret_cast<__half2*>(g_xbf + w * DD + lane * 4);
    dst[0] = __floats2half2_rn(v.x * s, v.y * s);
    dst[1] = __floats2half2_rn(v.z * s, v.w * s);
    if (lane == 0) g_ex[w] = expf(-gm * ss);
}

__global__ void prep_t_kernel(const float* __restrict__ t, const float* __restrict__ gamma,
                              const float* __restrict__ W) {
    int w = (blockIdx.x * blockDim.x + threadIdx.x) >> 5;
    int lane = threadIdx.x & 31;
    if (w >= NN) return;
    float4 v = reinterpret_cast<const float4*>(t + w * DD)[lane];
    float ss = v.x * v.x + v.y * v.y + v.z * v.z + v.w * v.w;
    #pragma unroll
    for (int o = 16; o > 0; o >>= 1) ss += __shfl_xor_sync(0xFFFFFFFFu, ss, o);
    __half2* dst = reinterpret_cast<__half2*>(g_tbf + w * DD + lane * 4);
    dst[0] = __floats2half2_rn(v.x, v.y);
    dst[1] = __floats2half2_rn(v.z, v.w);
    if (lane == 0) g_c1[w] = W[w] * expf(-gamma[0] * ss);
}

// ============================================================================
// Main kernel: hot loop identical to R13; grid is now 9x16=144 CTAs with a
// ragged N split (29,29,29,29,28,28,28,28,28 tiles) -> all-but-4 SMs busy,
// makespan 29 tiles instead of 32.
// ============================================================================
__global__ void __launch_bounds__(THREADS, 1)
rbf_main_kernel() {
    extern __shared__ char smem[];
    uint32_t sb = smem_u32(smem);
    int tid = threadIdx.x;
    int lane = tid & 31;
    int wid = tid >> 5;
    int warp_m = wid & 3;     // 4 warps along M (32 rows each)
    int warp_n = wid >> 2;    // 2 warps along N (64 cols each)
    int g  = lane >> 2;
    int tg = lane & 3;

    int m0 = blockIdx.y * BT;
    int ns = blockIdx.x;
    // Ragged split: first 4 splits get 29 tiles, the rest 28.
    int cnt    = 28 + (ns < 4 ? 1 : 0);
    int tstart = ns * 28 + (ns < 4 ? ns : 4);

    // Prologue: A tile + (B0,c1_0) group 0, (B1,c1_1) group 1
    issue_tile(sb + SMEM_A, g_xbf + (size_t)m0 * DD);
    issue_tile(sb + SMEM_B0, g_tbf + (size_t)tstart * NT * DD);
    issue_c1(sb + SMEM_C10, g_c1 + tstart * NT);
    CP_COMMIT();
    issue_tile(sb + SMEM_B1, g_tbf + (size_t)(tstart + 1) * NT * DD);
    issue_c1(sb + SMEM_C11, g_c1 + (tstart + 1) * NT);
    CP_COMMIT();

    int a_row_in_warp = ((lane >> 3) & 1) * 8 + (lane & 7);
    int a_kb16 = ((lane >> 4) & 1) * 16;
    int b_row_in_nb = lane & 7;
    int b_kb16 = (lane >> 3) * 16;

    asm volatile("cp.async.wait_group 1;" ::: "memory");  // A + B0 + c1_0 resident
    __syncthreads();

    // Hoist A fragments (constant across the whole tile loop)
    uint32_t af[4][2][2][4];   // [kq][ms][kk][4]
    #pragma unroll
    for (int kq = 0; kq < 4; kq++) {
        int chunk = kq >> 1;
        int kbyte0 = (kq & 1) * 64;
        uint32_t base = sb + SMEM_A + chunk * 16384;
        #pragma unroll
        for (int ms = 0; ms < 2; ms++) {
            int row = warp_m * 32 + ms * 16 + a_row_in_warp;
            ldsm4(af[kq][ms][0], base + SWZ((uint32_t)(row * 128 + kbyte0 + a_kb16)));
            ldsm4(af[kq][ms][1], base + SWZ((uint32_t)(row * 128 + kbyte0 + 32 + a_kb16)));
        }
    }

    float racc[2][2] = {{0.f, 0.f}, {0.f, 0.f}};

    for (int i = 0; i < cnt; i++) {
        if (i + 1 < cnt) { asm volatile("cp.async.wait_group 1;" ::: "memory"); }
        else             { asm volatile("cp.async.wait_group 0;" ::: "memory"); }
        __syncthreads();

        uint32_t Bb  = sb + ((i & 1) ? SMEM_B1  : SMEM_B0);
        uint32_t c1s = sb + ((i & 1) ? SMEM_C11 : SMEM_C10) + (warp_n * 64 + 2 * tg) * 4;

        // Pair-pipelined epilogue (R13 structure, measured == R11).
        float acc[2][2][2][4];   // [parity][nb2][ms][4]
        float2 wv[2][2];         // [parity][nb2]

        #pragma unroll
        for (int np = 0; np < 4; np++) {
            int p = np & 1;
            uint32_t bf[2][4][4];   // [nb2][kq][k-sub]
            #pragma unroll
            for (int nb2 = 0; nb2 < 2; nb2++) {
                int row = warp_n * 64 + (np * 2 + nb2) * 8 + b_row_in_nb;
                #pragma unroll
                for (int kq = 0; kq < 4; kq++) {
                    int chunk = kq >> 1;
                    int kbyte0 = (kq & 1) * 64;
                    ldsm4(bf[nb2][kq], Bb + chunk * 16384 +
                          SWZ((uint32_t)(row * 128 + kbyte0 + b_kb16)));
                }
            }
            #pragma unroll
            for (int nb2 = 0; nb2 < 2; nb2++) {
                wv[p][nb2] = lds64f(c1s + (np * 2 + nb2) * 32);
                #pragma unroll
                for (int ms = 0; ms < 2; ms++)
                    #pragma unroll
                    for (int c = 0; c < 4; c++) acc[p][nb2][ms][c] = 0.f;
            }
            #pragma unroll
            for (int kq = 0; kq < 4; kq++)
                #pragma unroll
                for (int kk = 0; kk < 2; kk++)
                    #pragma unroll
                    for (int nb2 = 0; nb2 < 2; nb2++)
                        #pragma unroll
                        for (int ms = 0; ms < 2; ms++)
                            mma16816(acc[p][nb2][ms], af[kq][ms][kk], &bf[nb2][kq][kk * 2]);

            if (np > 0) {  // epilogue of the PREVIOUS pair (parity p^1)
                int q = p ^ 1;
                #pragma unroll
                for (int nb2 = 0; nb2 < 2; nb2++) {
                    #pragma unroll
                    for (int ms = 0; ms < 2; ms++) {
                        racc[ms][0] = fmaf(ex2f(acc[q][nb2][ms][0]), wv[q][nb2].x, racc[ms][0]);
                        racc[ms][0] = fmaf(ex2f(acc[q][nb2][ms][1]), wv[q][nb2].y, racc[ms][0]);
                        racc[ms][1] = fmaf(ex2f(acc[q][nb2][ms][2]), wv[q][nb2].x, racc[ms][1]);
                        racc[ms][1] = fmaf(ex2f(acc[q][nb2][ms][3]), wv[q][nb2].y, racc[ms][1]);
                    }
                }
            }
        }
        // Drain epilogue of the last pair (np=3, parity 1)
        #pragma unroll
        for (int nb2 = 0; nb2 < 2; nb2++) {
            #pragma unroll
            for (int ms = 0; ms < 2; ms++) {
                racc[ms][0] = fmaf(ex2f(acc[1][nb2][ms][0]), wv[1][nb2].x, racc[ms][0]);
                racc[ms][0] = fmaf(ex2f(acc[1][nb2][ms][1]), wv[1][nb2].y, racc[ms][0]);
                racc[ms][1] = fmaf(ex2f(acc[1][nb2][ms][2]), wv[1][nb2].x, racc[ms][1]);
                racc[ms][1] = fmaf(ex2f(acc[1][nb2][ms][3]), wv[1][nb2].y, racc[ms][1]);
            }
        }

        __syncthreads();   // all warps done reading Bb + c1s
        if (i + 2 < cnt) {
            issue_tile(Bb, g_tbf + (size_t)(tstart + i + 2) * NT * DD);
            issue_c1(sb + ((i & 1) ? SMEM_C11 : SMEM_C10), g_c1 + (tstart + i + 2) * NT);
        }
        CP_COMMIT();
    }

    // Reduce over the 4 lanes sharing each row; write contiguous-per-b partials.
    #pragma unroll
    for (int ms = 0; ms < 2; ms++)
        #pragma unroll
        for (int h = 0; h < 2; h++) {
            float v = racc[ms][h];
            v += __shfl_xor_sync(0xFFFFFFFFu, v, 1);
            v += __shfl_xor_sync(0xFFFFFFFFu, v, 2);
            if (tg == 0) {
                int b = m0 + warp_m * 32 + ms * 16 + h * 8 + g;
                g_partial[b * PSLOTS + ns * 2 + warp_n] = v;
            }
        }
}

// ============================================================================
// Final reduction: out[b] = e_x[b] * sum(18 contiguous partials) + bias
// ============================================================================
__global__ void reduce_kernel(const float* __restrict__ bias, float* __restrict__ out) {
    int b = blockIdx.x * blockDim.x + threadIdx.x;
    if (b >= BB) return;
    const float2* p = reinterpret_cast<const float2*>(g_partial + b * PSLOTS);
    float s = 0.0f;
    #pragma unroll
    for (int k = 0; k < PSLOTS / 2; k++) {
        float2 v = p[k];
        s += v.x + v.y;
    }
    out[b] = fmaf(g_ex[b], s, __ldg(bias));
}

// ============================================================================
// Entry — 4-launch structure
// ============================================================================
extern "C" void kernel_launch(void* const* d_in, const int* in_sizes, int n_in,
                              void* d_out, int out_size) {
    const float* x     = (const float*)d_in[0];   // [2048, 128]
    const float* train = (const float*)d_in[1];   // [32768, 128]
    const float* gamma = (const float*)d_in[2];   // [1]
    const float* W     = (const float*)d_in[3];   // [1, 32768]
    const float* bias  = (const float*)d_in[4];   // [1]
    float* out = (float*)d_out;                   // [2048, 1]

    cudaFuncSetAttribute(rbf_main_kernel,
                         cudaFuncAttributeMaxDynamicSharedMemorySize, SMEM_TOTAL);

    prep_x_kernel<<<(BB * 32) / THREADS, THREADS>>>(x, gamma);
    prep_t_kernel<<<(NN * 32) / THREADS, THREADS>>>(train, gamma, W);
    rbf_main_kernel<<<dim3(NSPLITS, BTILES), THREADS, SMEM_TOTAL>>>();
    reduce_kernel<<<BB / THREADS, THREADS>>>(bias, out);
}